// round 9
// baseline (speedup 1.0000x reference)
#include <cuda_runtime.h>
#include <cuda_bf16.h>

// logits[r] = sum_d fc[r][d] * input[d],  r in [0,50), D = 2^20.
//
// Round-3 profile showed: (a) reduce_kernel = 4.4us of pure launch overhead,
// (b) main kernel ~33us consistent with LTS cap on 400MB of L2 traffic
//     (200MB fc + 200MB input re-read 50x).
//
// This version:
//  - Row-grouping: each block caches a 4096-float input chunk in REGISTERS
//    and dots it against 10 fc rows -> input L2 traffic 200MB -> 20MB.
//  - Single launch: threadfence-counter pattern; last block per row-group
//    reduces partials and writes d_out, then resets its counter (deterministic
//    under graph replay).

#define D_ELEMS     (1 << 20)
#define N_ROWS      50
#define TPB         256
#define V4_PER_T    4
#define CHUNK_F     (TPB * V4_PER_T * 4)        // 4096 floats per chunk
#define N_CHUNKS    (D_ELEMS / CHUNK_F)         // 256
#define ROWS_PER_G  10
#define N_GROUPS    (N_ROWS / ROWS_PER_G)       // 5

__device__ float g_partials[N_ROWS * N_CHUNKS];
// One counter per row-group, padded to separate cache lines. Zero-initialized
// statically; each use resets it, so every graph replay starts from 0.
__device__ unsigned int g_count[N_GROUPS * 32];

__global__ __launch_bounds__(TPB) void matvec_fused_kernel(
    const float4* __restrict__ inp,   // [D/4]
    const float4* __restrict__ fc,    // [N_ROWS * D/4]
    float* __restrict__ out)          // [N_ROWS]
{
    const int chunk = blockIdx.x;     // 0..N_CHUNKS-1
    const int grp   = blockIdx.y;     // 0..N_GROUPS-1
    const int t     = threadIdx.x;
    const int row0  = grp * ROWS_PER_G;

    // ---- Cache this block's input chunk in registers (read once from L2) ----
    const float4* a = inp + (size_t)chunk * (CHUNK_F / 4);
    float4 av[V4_PER_T];
#pragma unroll
    for (int i = 0; i < V4_PER_T; i++)
        av[i] = __ldg(&a[t + i * TPB]);

    // ---- Stream 10 fc rows against the cached input ----
    float acc[ROWS_PER_G];
#pragma unroll
    for (int r = 0; r < ROWS_PER_G; r++) {
        const float4* b = fc + (size_t)(row0 + r) * (D_ELEMS / 4)
                             + (size_t)chunk * (CHUNK_F / 4);
        float4 bv[V4_PER_T];
#pragma unroll
        for (int i = 0; i < V4_PER_T; i++)
            bv[i] = __ldg(&b[t + i * TPB]);

        float s = 0.0f;
#pragma unroll
        for (int i = 0; i < V4_PER_T; i++) {
            s += av[i].x * bv[i].x;
            s += av[i].y * bv[i].y;
            s += av[i].z * bv[i].z;
            s += av[i].w * bv[i].w;
        }
        acc[r] = s;
    }

    // ---- Block-reduce each of the 10 sums; thread 0 writes partials ----
    __shared__ float s_red[ROWS_PER_G][TPB / 32];
#pragma unroll
    for (int r = 0; r < ROWS_PER_G; r++) {
        float s = acc[r];
#pragma unroll
        for (int off = 16; off > 0; off >>= 1)
            s += __shfl_down_sync(0xFFFFFFFFu, s, off);
        if ((t & 31) == 0) s_red[r][t >> 5] = s;
    }
    __syncthreads();

    if (t < ROWS_PER_G) {
        float v = 0.0f;
#pragma unroll
        for (int w = 0; w < TPB / 32; w++)
            v += s_red[t][w];
        g_partials[(size_t)(row0 + t) * N_CHUNKS + chunk] = v;
    }

    // ---- Last block of this row-group does the final reduction ----
    __shared__ unsigned int s_is_last;
    __threadfence();              // make partials visible chip-wide
    __syncthreads();              // all warps' partial writes issued
    if (t == 0) {
        unsigned int prev = atomicAdd(&g_count[grp * 32], 1u);
        s_is_last = (prev == N_CHUNKS - 1) ? 1u : 0u;
    }
    __syncthreads();
    if (!s_is_last) return;

    __threadfence();              // acquire: see all other blocks' partials

    // Reduce 10 rows x 256 chunks. 256 threads: one chunk value per thread.
    __shared__ float s_fin[TPB / 32];
    const volatile float* vp = g_partials;
#pragma unroll
    for (int r = 0; r < ROWS_PER_G; r++) {
        float v = vp[(size_t)(row0 + r) * N_CHUNKS + t];
#pragma unroll
        for (int off = 16; off > 0; off >>= 1)
            v += __shfl_down_sync(0xFFFFFFFFu, v, off);
        if ((t & 31) == 0) s_fin[t >> 5] = v;
        __syncthreads();
        if (t == 0) {
            float sum = 0.0f;
#pragma unroll
            for (int w = 0; w < TPB / 32; w++)
                sum += s_fin[w];
            out[row0 + r] = sum;
        }
        __syncthreads();
    }

    // Reset counter for the next (graph-replayed) launch.
    if (t == 0)
        atomicExch(&g_count[grp * 32], 0u);
}

extern "C" void kernel_launch(void* const* d_in, const int* in_sizes, int n_in,
                              void* d_out, int out_size)
{
    // Disambiguate operands by element count (robust to metadata ordering).
    const float4* inp;
    const float4* fc;
    if (in_sizes[0] == D_ELEMS) {
        inp = (const float4*)d_in[0];
        fc  = (const float4*)d_in[1];
    } else {
        fc  = (const float4*)d_in[0];
        inp = (const float4*)d_in[1];
    }
    float* out = (float*)d_out;

    dim3 grid(N_CHUNKS, N_GROUPS);
    matvec_fused_kernel<<<grid, TPB>>>(inp, fc, out);
}